// round 1
// baseline (speedup 1.0000x reference)
#include <cuda_runtime.h>

// ---------------------------------------------------------------------------
// SpatialFrequencyLoss: sum_i w_i * mean( (LoG_i * (input - target))^2 )
// LoG kernel is rank-3 separable:  a = f (x) u  +  u (x) f  -  c * ones
// Row pass (along W): A_f = diff*f, A_h = diff*u, A_1 = diff*ones (box)
// Col pass (along H): d = f*A_h + u*A_f - c*A_1 ; accumulate d^2
// Reflect padding (numpy 'reflect', no edge repeat), pad = K/2 < 512 always.
// ---------------------------------------------------------------------------

namespace {
constexpr int Hh = 512, Ww = 512, NCc = 4 * 3;
constexpr int NPIX = NCc * Hh * Ww;  // 3,145,728
}

__device__ float g_diff[NPIX];
__device__ float g_Af[NPIX];
__device__ float g_Ah[NPIX];
__device__ float g_A1[NPIX];
__device__ double g_acc[6];

// ---------------- compile-time taps ----------------------------------------

__host__ __device__ constexpr double cexp(double x) {
    // x in [-17, 0]; reduce to (-0.5, 0], 30-term series, scale by e^-n
    double r = x; int n = 0;
    while (r < -0.5) { r += 1.0; ++n; }
    double term = 1.0, sum = 1.0;
    for (int i = 1; i < 30; ++i) { term *= r / (double)i; sum += term; }
    for (int i = 0; i < n; ++i) sum /= 2.71828182845904523536028747135266;
    return sum;
}

template<int K> struct TapsT { float f[K]; float h[K]; float c; };

template<int K>
__host__ __device__ constexpr TapsT<K> make_taps(double sigma) {
    TapsT<K> T{};
    const double ss = sigma * sigma;
    const double norm = 1.0 / (2.0 * 3.14159265358979323846 * ss * ss);
    double Sf = 0.0, Sh = 0.0;
    for (int i = 0; i < K; ++i) {
        const double x = (double)(i - (K - 1) / 2);
        const double u = cexp(-(x * x) / (2.0 * ss));
        const double fv = (x * x - ss) * u * norm;
        T.f[i] = (float)fv;
        T.h[i] = (float)u;
        Sf += fv; Sh += u;
    }
    // c = sum(a_pre)/K^2 = 2*Sf*Sh/K^2  (a_pre = f(x)u(y)+u(x)f(y))
    T.c = (float)(2.0 * Sf * Sh / ((double)K * (double)K));
    return T;
}

template<int SI> struct Cfg;
template<> struct Cfg<0> { static constexpr int K = 5;   static constexpr double S = 0.6;  };
template<> struct Cfg<1> { static constexpr int K = 11;  static constexpr double S = 1.2;  };
template<> struct Cfg<2> { static constexpr int K = 21;  static constexpr double S = 2.4;  };
template<> struct Cfg<3> { static constexpr int K = 39;  static constexpr double S = 4.8;  };
template<> struct Cfg<4> { static constexpr int K = 77;  static constexpr double S = 9.6;  };
template<> struct Cfg<5> { static constexpr int K = 155; static constexpr double S = 19.2; };

// ---------------- helpers ---------------------------------------------------

__device__ __forceinline__ int refl(int i, int n) {
    if (i < 0) i = -i;
    if (i >= n) i = 2 * n - 2 - i;
    return i;
}

// ---------------- kernels ---------------------------------------------------

__global__ void zero_acc_k() {
    if (threadIdx.x < 6) g_acc[threadIdx.x] = 0.0;
}

__global__ void diff_k(const float4* __restrict__ a, const float4* __restrict__ b) {
    int i = blockIdx.x * blockDim.x + threadIdx.x;
    if (i < NPIX / 4) {
        float4 x = a[i], y = b[i];
        float4 d;
        d.x = x.x - y.x; d.y = x.y - y.y; d.z = x.z - y.z; d.w = x.w - y.w;
        reinterpret_cast<float4*>(g_diff)[i] = d;
    }
}

// Row pass: one block per (n,c,y) row; 128 threads, 4 consecutive outputs each.
template<int SI>
__global__ void __launch_bounds__(128) row_k() {
    constexpr int K = Cfg<SI>::K;
    constexpr TapsT<K> T = make_taps<K>(Cfg<SI>::S);
    constexpr int P = K / 2;
    constexpr int PW = Ww + 2 * P;

    __shared__ float s[PW];
    const int row = blockIdx.x;
    const float* __restrict__ src = g_diff + row * Ww;
    for (int i = threadIdx.x; i < PW; i += 128) s[i] = src[refl(i - P, Ww)];
    __syncthreads();

    const int x0 = threadIdx.x * 4;
    float r[4];
    r[0] = s[x0]; r[1] = s[x0 + 1]; r[2] = s[x0 + 2]; r[3] = 0.f;
    float aF[4] = {0.f, 0.f, 0.f, 0.f};
    float aH[4] = {0.f, 0.f, 0.f, 0.f};
    float aB[4] = {0.f, 0.f, 0.f, 0.f};

#pragma unroll
    for (int t = 0; t < K; ++t) {
        r[(t + 3) & 3] = s[x0 + t + 3];
#pragma unroll
        for (int o = 0; o < 4; ++o) {
            const float d = r[(t + o) & 3];
            aF[o] = fmaf(T.f[t], d, aF[o]);
            aH[o] = fmaf(T.h[t], d, aH[o]);
            aB[o] += d;
        }
    }

    const int base = row * Ww + x0;
    *reinterpret_cast<float4*>(g_Af + base) = make_float4(aF[0], aF[1], aF[2], aF[3]);
    *reinterpret_cast<float4*>(g_Ah + base) = make_float4(aH[0], aH[1], aH[2], aH[3]);
    *reinterpret_cast<float4*>(g_A1 + base) = make_float4(aB[0], aB[1], aB[2], aB[3]);
}

// Col pass: each thread owns one x column, 8 consecutive y outputs, register
// ring of 8 rows per plane. d = f*A_h + u*A_f - c*A_1; accumulate d^2.
template<int SI>
__global__ void __launch_bounds__(128) col_k() {
    constexpr int K = Cfg<SI>::K;
    constexpr TapsT<K> T = make_taps<K>(Cfg<SI>::S);
    constexpr int P = K / 2;
    constexpr int R = 8;

    const int x  = blockIdx.x * 128 + threadIdx.x;
    const int y0 = blockIdx.y * R;
    const int pb = blockIdx.z * (Hh * Ww) + x;

    float ah[R], af[R], a1[R], acc[R], bac[R];
#pragma unroll
    for (int o = 0; o < R; ++o) { acc[o] = 0.f; bac[o] = 0.f; }

    // prologue: rows 0 .. R-2 (offset from y0 - P), slot = rowidx & 7
#pragma unroll
    for (int j = 0; j < R - 1; ++j) {
        const int yy  = refl(y0 - P + j, Hh);
        const int idx = pb + yy * Ww;
        ah[j] = g_Ah[idx]; af[j] = g_Af[idx]; a1[j] = g_A1[idx];
    }

#pragma unroll
    for (int t = 0; t < K; ++t) {
        const int yy  = refl(y0 - P + t + (R - 1), Hh);
        const int idx = pb + yy * Ww;
        const int sl  = (t + R - 1) & (R - 1);
        ah[sl] = g_Ah[idx]; af[sl] = g_Af[idx]; a1[sl] = g_A1[idx];
#pragma unroll
        for (int o = 0; o < R; ++o) {
            const int u = (t + o) & (R - 1);
            acc[o] = fmaf(T.f[t], ah[u], acc[o]);
            acc[o] = fmaf(T.h[t], af[u], acc[o]);
            bac[o] += a1[u];
        }
    }

    float local = 0.f;
#pragma unroll
    for (int o = 0; o < R; ++o) {
        const float v = fmaf(-T.c, bac[o], acc[o]);
        local = fmaf(v, v, local);
    }

    // block reduction -> one double atomic per block
#pragma unroll
    for (int off = 16; off; off >>= 1)
        local += __shfl_xor_sync(0xffffffffu, local, off);
    __shared__ float ws[4];
    if ((threadIdx.x & 31) == 0) ws[threadIdx.x >> 5] = local;
    __syncthreads();
    if (threadIdx.x == 0) {
        const double tot = (double)ws[0] + (double)ws[1] + (double)ws[2] + (double)ws[3];
        atomicAdd(&g_acc[SI], tot);
    }
}

__global__ void final_k(float* __restrict__ out) {
    const double w[6] = {600.0, 500.0, 400.0, 20.0, 10.0, 10.0};
    double l = 0.0;
    for (int i = 0; i < 6; ++i) l += w[i] * g_acc[i];
    out[0] = (float)(l / (double)NPIX);
}

// ---------------- launcher ---------------------------------------------------

template<int SI> static void run_sigma() {
    row_k<SI><<<NCc * Hh, 128>>>();
    col_k<SI><<<dim3(Ww / 128, Hh / 8, NCc), 128>>>();
}

extern "C" void kernel_launch(void* const* d_in, const int* in_sizes, int n_in,
                              void* d_out, int out_size) {
    (void)in_sizes; (void)n_in; (void)out_size;
    const float4* a = (const float4*)d_in[0];
    const float4* b = (const float4*)d_in[1];

    zero_acc_k<<<1, 32>>>();
    diff_k<<<(NPIX / 4) / 512, 512>>>(a, b);
    run_sigma<0>();
    run_sigma<1>();
    run_sigma<2>();
    run_sigma<3>();
    run_sigma<4>();
    run_sigma<5>();
    final_k<<<1, 1>>>((float*)d_out);
}

// round 2
// speedup vs baseline: 1.1793x; 1.1793x over previous
#include <cuda_runtime.h>

// ---------------------------------------------------------------------------
// SpatialFrequencyLoss: sum_i w_i * mean( (LoG_i * (input - target))^2 )
// LoG kernel is rank-3 separable:  a = f (x) u  +  u (x) f  -  c * ones
// Row pass (along W): FH = (diff*f, diff*u) interleaved, A1 = diff*box
// Col pass (along H): d = f*Ah + u*Af - c*Box ; accumulate d^2
// Box terms use sliding-window updates (O(1) per extra output).
// Reflect padding (numpy 'reflect'), pad = K/2 < 512 always.
// ---------------------------------------------------------------------------

namespace {
constexpr int Hh = 512, Ww = 512, NCc = 4 * 3;
constexpr int NPIX = NCc * Hh * Ww;  // 3,145,728
}

__device__ float  g_diff[NPIX];
__device__ float4 g_FH[NPIX / 2];    // (Af,Ah) pairs, two pixels per float4
__device__ float4 g_A14[NPIX / 4];   // A1 plane, float4-aligned
__device__ double g_acc[6];

// ---------------- compile-time taps ----------------------------------------

__host__ __device__ constexpr double cexp(double x) {
    double r = x; int n = 0;
    while (r < -0.5) { r += 1.0; ++n; }
    double term = 1.0, sum = 1.0;
    for (int i = 1; i < 30; ++i) { term *= r / (double)i; sum += term; }
    for (int i = 0; i < n; ++i) sum /= 2.71828182845904523536028747135266;
    return sum;
}

template<int K> struct TapsT { float f[K]; float h[K]; float c; };

template<int K>
__host__ __device__ constexpr TapsT<K> make_taps(double sigma) {
    TapsT<K> T{};
    const double ss = sigma * sigma;
    const double norm = 1.0 / (2.0 * 3.14159265358979323846 * ss * ss);
    double Sf = 0.0, Sh = 0.0;
    for (int i = 0; i < K; ++i) {
        const double x = (double)(i - (K - 1) / 2);
        const double u = cexp(-(x * x) / (2.0 * ss));
        const double fv = (x * x - ss) * u * norm;
        T.f[i] = (float)fv;
        T.h[i] = (float)u;
        Sf += fv; Sh += u;
    }
    T.c = (float)(2.0 * Sf * Sh / ((double)K * (double)K));
    return T;
}

template<int SI> struct Cfg;
template<> struct Cfg<0> { static constexpr int K = 5;   static constexpr double S = 0.6;  };
template<> struct Cfg<1> { static constexpr int K = 11;  static constexpr double S = 1.2;  };
template<> struct Cfg<2> { static constexpr int K = 21;  static constexpr double S = 2.4;  };
template<> struct Cfg<3> { static constexpr int K = 39;  static constexpr double S = 4.8;  };
template<> struct Cfg<4> { static constexpr int K = 77;  static constexpr double S = 9.6;  };
template<> struct Cfg<5> { static constexpr int K = 155; static constexpr double S = 19.2; };

__device__ __forceinline__ int refl(int i, int n) {
    if (i < 0) i = -i;
    if (i >= n) i = 2 * n - 2 - i;
    return i;
}

// ---------------- kernels ---------------------------------------------------

__global__ void diff_k(const float4* __restrict__ a, const float4* __restrict__ b) {
    if (blockIdx.x == 0 && threadIdx.x < 6) g_acc[threadIdx.x] = 0.0;
    int i = blockIdx.x * blockDim.x + threadIdx.x;
    if (i < NPIX / 4) {
        float4 x = a[i], y = b[i];
        float4 d;
        d.x = x.x - y.x; d.y = x.y - y.y; d.z = x.z - y.z; d.w = x.w - y.w;
        reinterpret_cast<float4*>(g_diff)[i] = d;
    }
}

// Row pass: 128 threads = 2 rows x 64 threads; 8 consecutive outputs/thread.
template<int SI>
__global__ void __launch_bounds__(128) row_k() {
    constexpr int K = Cfg<SI>::K;
    constexpr TapsT<K> T = make_taps<K>(Cfg<SI>::S);
    constexpr int P = K / 2;
    constexpr int PW = Ww + 2 * P;
    constexpr int R = 8;

    __shared__ float s[2][PW];
    const int row0 = blockIdx.x * 2;
#pragma unroll
    for (int rr = 0; rr < 2; ++rr) {
        const float* __restrict__ src = g_diff + (row0 + rr) * Ww;
        for (int i = threadIdx.x; i < PW; i += 128) s[rr][i] = src[refl(i - P, Ww)];
    }
    __syncthreads();

    const int sub = threadIdx.x >> 6;          // which of the 2 rows
    const int x0  = (threadIdx.x & 63) * R;    // first output col
    const float* __restrict__ sr = s[sub];

    float r[R];
#pragma unroll
    for (int j = 0; j < R - 1; ++j) r[j] = sr[x0 + j];
    float aF[R], aH[R];
#pragma unroll
    for (int o = 0; o < R; ++o) { aF[o] = 0.f; aH[o] = 0.f; }
    float S = 0.f;

#pragma unroll
    for (int t = 0; t < K; ++t) {
        r[(t + R - 1) & (R - 1)] = sr[x0 + t + R - 1];
        S += r[t & (R - 1)];   // box for output 0
#pragma unroll
        for (int o = 0; o < R; ++o) {
            const float d = r[(t + o) & (R - 1)];
            aF[o] = fmaf(T.f[t], d, aF[o]);
            aH[o] = fmaf(T.h[t], d, aH[o]);
        }
    }

    // sliding box for outputs 1..R-1
    float box[R];
    box[0] = S;
#pragma unroll
    for (int o = 1; o < R; ++o)
        box[o] = box[o - 1] - sr[x0 + o - 1] + sr[x0 + o + K - 1];

    const int base = (row0 + sub) * Ww + x0;   // multiple of 8
    float4* __restrict__ fh = g_FH + base / 2;
#pragma unroll
    for (int o = 0; o < R; o += 2)
        fh[o / 2] = make_float4(aF[o], aH[o], aF[o + 1], aH[o + 1]);
    float4* __restrict__ a1 = g_A14 + base / 4;
    a1[0] = make_float4(box[0], box[1], box[2], box[3]);
    a1[1] = make_float4(box[4], box[5], box[6], box[7]);
}

// Col pass body. FAST => no reflection needed for any accessed row.
template<int SI, bool FAST>
__device__ __forceinline__ float col_body(int pb, int y0) {
    constexpr int K = Cfg<SI>::K;
    constexpr TapsT<K> T = make_taps<K>(Cfg<SI>::S);
    constexpr int P = K / 2;
    constexpr int R = 16;

    const float2* __restrict__ FH = (const float2*)g_FH;
    const float*  __restrict__ A1 = (const float*)g_A14;
    const int yb = y0 - P;

    auto rowidx = [&](int j) -> int {
        return pb + (FAST ? (yb + j) : refl(yb + j, Hh)) * Ww;
    };

    float af[R], ah[R], acc[R];
#pragma unroll
    for (int o = 0; o < R; ++o) acc[o] = 0.f;
    float S = 0.f;

#pragma unroll
    for (int j = 0; j < R - 1; ++j) {
        const int idx = rowidx(j);
        const float2 v = FH[idx];
        af[j] = v.x; ah[j] = v.y;
        if (j <= K - 1) S += A1[idx];
    }

#pragma unroll
    for (int t = 0; t < K; ++t) {
        const int j = t + R - 1;
        const int idx = rowidx(j);
        const int sl = j & (R - 1);
        const float2 v = FH[idx];
        af[sl] = v.x; ah[sl] = v.y;
        if (j <= K - 1) S += A1[idx];
#pragma unroll
        for (int o = 0; o < R; ++o) {
            const int u = (t + o) & (R - 1);
            acc[o] = fmaf(T.f[t], ah[u], acc[o]);
            acc[o] = fmaf(T.h[t], af[u], acc[o]);
        }
    }

    // sliding box across the 16 outputs
    float lo[R], hi[R];
#pragma unroll
    for (int o = 1; o < R; ++o) {
        lo[o] = A1[rowidx(o - 1)];
        hi[o] = A1[rowidx(K - 1 + o)];
    }
    float box = S, local = 0.f;
#pragma unroll
    for (int o = 0; o < R; ++o) {
        if (o) box += hi[o] - lo[o];
        const float v = fmaf(-T.c, box, acc[o]);
        local = fmaf(v, v, local);
    }
    return local;
}

template<int SI>
__global__ void __launch_bounds__(128) col_k() {
    constexpr int K = Cfg<SI>::K;
    constexpr int P = K / 2;
    constexpr int R = 16;

    const int x  = blockIdx.x * 128 + threadIdx.x;
    const int y0 = blockIdx.y * R;
    const int pb = blockIdx.z * (Hh * Ww) + x;

    const bool interior = (y0 - P >= 0) && (y0 - P + K + R - 2 < Hh);
    float local = interior ? col_body<SI, true>(pb, y0)
                           : col_body<SI, false>(pb, y0);

#pragma unroll
    for (int off = 16; off; off >>= 1)
        local += __shfl_xor_sync(0xffffffffu, local, off);
    __shared__ float ws[4];
    if ((threadIdx.x & 31) == 0) ws[threadIdx.x >> 5] = local;
    __syncthreads();
    if (threadIdx.x == 0) {
        const double tot = (double)ws[0] + (double)ws[1] + (double)ws[2] + (double)ws[3];
        atomicAdd(&g_acc[SI], tot);
    }
}

__global__ void final_k(float* __restrict__ out) {
    const double w[6] = {600.0, 500.0, 400.0, 20.0, 10.0, 10.0};
    double l = 0.0;
    for (int i = 0; i < 6; ++i) l += w[i] * g_acc[i];
    out[0] = (float)(l / (double)NPIX);
}

// ---------------- launcher ---------------------------------------------------

template<int SI> static void run_sigma() {
    row_k<SI><<<NCc * Hh / 2, 128>>>();
    col_k<SI><<<dim3(Ww / 128, Hh / 16, NCc), 128>>>();
}

extern "C" void kernel_launch(void* const* d_in, const int* in_sizes, int n_in,
                              void* d_out, int out_size) {
    (void)in_sizes; (void)n_in; (void)out_size;
    const float4* a = (const float4*)d_in[0];
    const float4* b = (const float4*)d_in[1];

    diff_k<<<(NPIX / 4 + 511) / 512, 512>>>(a, b);
    run_sigma<0>();
    run_sigma<1>();
    run_sigma<2>();
    run_sigma<3>();
    run_sigma<4>();
    run_sigma<5>();
    final_k<<<1, 1>>>((float*)d_out);
}